// round 7
// baseline (speedup 1.0000x reference)
#include <cuda_runtime.h>
#include <cuda_bf16.h>
#include <cstdint>

// Problem constants
#define BB 2
#define NN 2048
#define HH 16
#define DH 64
#define DD 1024          // HH*DH
#define D3 3072          // 3*DD
#define MM 4096          // BB*NN

// Scratch: QKV laid out [part(q/k/v)][B][H][N][Dh]
__device__ float g_qkv[3u * BB * HH * NN * DH];
// tf32 hi/lo splits, k pre-permuted within each 8-block: [k0,k4,k1,k5,k2,k6,k3,k7]
__device__ float g_xhi[(size_t)MM * DD];     // [m][k']
__device__ float g_xlo[(size_t)MM * DD];
__device__ float g_whiT[(size_t)D3 * DD];    // [n][k']
__device__ float g_wloT[(size_t)D3 * DD];

// ---------------------------------------------------------------------------
// helpers
// ---------------------------------------------------------------------------
__device__ __forceinline__ float tf32_rna(float x) {
    uint32_t u;
    asm("cvt.rna.tf32.f32 %0, %1;" : "=r"(u) : "f"(x));
    return __uint_as_float(u);
}

#define CP_ASYNC16(dst_u32, gptr)                                              \
    asm volatile("cp.async.cg.shared.global [%0], [%1], 16;"                    \
                 :: "r"(dst_u32), "l"(__cvta_generic_to_global(gptr)))
#define CP_COMMIT() asm volatile("cp.async.commit_group;" ::: "memory")
#define CP_WAIT1()  asm volatile("cp.async.wait_group 1;" ::: "memory")
#define CP_WAIT0()  asm volatile("cp.async.wait_group 0;" ::: "memory")

__device__ __forceinline__ uint32_t smem_u32(const void* p) {
    uint32_t a;
    asm("{ .reg .u64 t; cvta.to.shared.u64 t, %1; cvt.u32.u64 %0, t; }"
        : "=r"(a) : "l"(p));
    return a;
}

// mma.sync m16n8k8 tf32: d += a * b
// a regs: a0=(r0,c) a1=(r1,c) a2=(r0,c+4) a3=(r1,c+4); b: b0=(k c,n g) b1=(k c+4,n g)
__device__ __forceinline__ void mma_tf32(float* d,
                                         uint32_t a0, uint32_t a1, uint32_t a2, uint32_t a3,
                                         uint32_t b0, uint32_t b1) {
    asm volatile(
        "mma.sync.aligned.m16n8k8.row.col.f32.tf32.tf32.f32 "
        "{%0,%1,%2,%3}, {%4,%5,%6,%7}, {%8,%9}, {%0,%1,%2,%3};"
        : "+f"(d[0]), "+f"(d[1]), "+f"(d[2]), "+f"(d[3])
        : "r"(a0), "r"(a1), "r"(a2), "r"(a3), "r"(b0), "r"(b1));
}

// ---------------------------------------------------------------------------
// Prep kernels: tf32 hi/lo split, k-permutation (+ transpose for W)
// ---------------------------------------------------------------------------
__global__ __launch_bounds__(256)
void prep_x(const float* __restrict__ X)
{
    const size_t n8 = (size_t)MM * DD / 8;
    for (size_t i = blockIdx.x * 256 + threadIdx.x; i < n8; i += (size_t)gridDim.x * 256) {
        const float* src = X + i * 8;
        float4 v0 = *(const float4*)(src);
        float4 v1 = *(const float4*)(src + 4);
        float s[8] = {v0.x, v0.y, v0.z, v0.w, v1.x, v1.y, v1.z, v1.w};
        float hi[8], lo[8];
#pragma unroll
        for (int k = 0; k < 8; ++k) {
            hi[k] = tf32_rna(s[k]);
            lo[k] = tf32_rna(s[k] - hi[k]);
        }
        // dest order: k0,k4,k1,k5,k2,k6,k3,k7
        float4 h0 = make_float4(hi[0], hi[4], hi[1], hi[5]);
        float4 h1 = make_float4(hi[2], hi[6], hi[3], hi[7]);
        float4 l0 = make_float4(lo[0], lo[4], lo[1], lo[5]);
        float4 l1 = make_float4(lo[2], lo[6], lo[3], lo[7]);
        *(float4*)(g_xhi + i * 8)     = h0;
        *(float4*)(g_xhi + i * 8 + 4) = h1;
        *(float4*)(g_xlo + i * 8)     = l0;
        *(float4*)(g_xlo + i * 8 + 4) = l1;
    }
}

__device__ __forceinline__ int kperm8(int k) {
    // position of source-k within its 8-block after permutation
    return (k & ~7) | (((k & 3) << 1) | ((k >> 2) & 1));
}

__global__ __launch_bounds__(256)
void prep_w(const float* __restrict__ W)
{
    __shared__ float t[32][33];
    const int n0 = blockIdx.x * 32;
    const int k0 = blockIdx.y * 32;
    const int tx = threadIdx.x, ty = threadIdx.y;   // (32, 8)
#pragma unroll
    for (int rr = 0; rr < 32; rr += 8)
        t[ty + rr][tx] = W[(size_t)(k0 + ty + rr) * D3 + n0 + tx];   // t[kk][nn]
    __syncthreads();
#pragma unroll
    for (int rr = 0; rr < 32; rr += 8) {
        float v  = t[tx][ty + rr];          // kk = tx, nn = ty+rr
        float hi = tf32_rna(v);
        float lo = tf32_rna(v - hi);
        size_t base = (size_t)(n0 + ty + rr) * DD + k0 + kperm8(tx);
        g_whiT[base] = hi;
        g_wloT[base] = lo;
    }
}

// ---------------------------------------------------------------------------
// tf32x3 QKV GEMM via mma.sync m16n8k8.
// CTA 128x128, 256 threads (warps 4m x 2n, warp tile 32x64), k-chunk 16,
// cp.async double buffer. Stage: Ahi|Alo|Bhi|Blo each 128x16 f32 = 32KB.
// ---------------------------------------------------------------------------
#define ST_FLOATS 8192          // 32KB per stage in floats
#define OAHI 0
#define OALO 2048
#define OBHI 4096
#define OBLO 6144
#define GEMM_SMEM_TOTAL (2 * ST_FLOATS * 4)

__device__ __forceinline__ void gemm_load(int kt, float* st, uint32_t st_u32,
                                          int m0, int n0, int tid)
{
    const int k0 = kt * 16;
    // each matrix-half: 128 rows x 16 floats = 512 float4; 256 threads x 2
#pragma unroll
    for (int it = 0; it < 2; ++it) {
        int j   = it * 256 + tid;
        int row = j >> 2;
        int q   = (j & 3) * 4;
        uint32_t doff = (uint32_t)(row * 16 + q) * 4;
        CP_ASYNC16(st_u32 + OAHI * 4 + doff, g_xhi  + (size_t)(m0 + row) * DD + k0 + q);
        CP_ASYNC16(st_u32 + OALO * 4 + doff, g_xlo  + (size_t)(m0 + row) * DD + k0 + q);
        CP_ASYNC16(st_u32 + OBHI * 4 + doff, g_whiT + (size_t)(n0 + row) * DD + k0 + q);
        CP_ASYNC16(st_u32 + OBLO * 4 + doff, g_wloT + (size_t)(n0 + row) * DD + k0 + q);
    }
}

__global__ __launch_bounds__(256, 1)
void qkv_gemm_mma()
{
    extern __shared__ float sm[];
    const int tid   = threadIdx.x;
    const int wid   = tid >> 5;
    const int lane  = tid & 31;
    const int warpm = wid & 3;        // 4 warps over m (32 rows each)
    const int warpn = wid >> 2;       // 2 warps over n (64 cols each)
    const int c     = lane & 3;
    const int g     = lane >> 2;
    const int n0    = blockIdx.x * 128;
    const int m0    = blockIdx.y * 128;

    float* st[2] = {sm, sm + ST_FLOATS};
    uint32_t stu[2] = {smem_u32(sm), smem_u32(sm + ST_FLOATS)};

    float acc[2][8][4];
#pragma unroll
    for (int mt = 0; mt < 2; ++mt)
#pragma unroll
        for (int nt = 0; nt < 8; ++nt)
#pragma unroll
            for (int v = 0; v < 4; ++v) acc[mt][nt][v] = 0.0f;

    gemm_load(0, st[0], stu[0], m0, n0, tid); CP_COMMIT();
    gemm_load(1, st[1], stu[1], m0, n0, tid); CP_COMMIT();

    for (int kt = 0; kt < 64; ++kt) {
        const int buf = kt & 1;
        if (kt < 62) { CP_WAIT1(); } else { CP_WAIT0(); }
        __syncthreads();

        const float* S = st[buf];
#pragma unroll
        for (int ks = 0; ks < 2; ++ks) {
            const int kc = ks * 8 + 2 * c;
            // A fragments: [mt][row-half] pairs (col c | c+4)
            float2 ah[2][2], al[2][2];
#pragma unroll
            for (int mt = 0; mt < 2; ++mt) {
                int rbase = warpm * 32 + mt * 16 + g;
                ah[mt][0] = *(const float2*)&S[OAHI + rbase * 16 + kc];
                ah[mt][1] = *(const float2*)&S[OAHI + (rbase + 8) * 16 + kc];
                al[mt][0] = *(const float2*)&S[OALO + rbase * 16 + kc];
                al[mt][1] = *(const float2*)&S[OALO + (rbase + 8) * 16 + kc];
            }
#pragma unroll
            for (int nt = 0; nt < 8; ++nt) {
                int nb = (warpn * 64 + nt * 8 + g) * 16 + kc;
                float2 bh = *(const float2*)&S[OBHI + nb];
                float2 bl = *(const float2*)&S[OBLO + nb];
                uint32_t bh0 = __float_as_uint(bh.x), bh1 = __float_as_uint(bh.y);
                uint32_t bl0 = __float_as_uint(bl.x), bl1 = __float_as_uint(bl.y);
#pragma unroll
                for (int mt = 0; mt < 2; ++mt) {
                    uint32_t ah0 = __float_as_uint(ah[mt][0].x);
                    uint32_t ah1 = __float_as_uint(ah[mt][1].x);
                    uint32_t ah2 = __float_as_uint(ah[mt][0].y);
                    uint32_t ah3 = __float_as_uint(ah[mt][1].y);
                    uint32_t al0 = __float_as_uint(al[mt][0].x);
                    uint32_t al1 = __float_as_uint(al[mt][1].x);
                    uint32_t al2 = __float_as_uint(al[mt][0].y);
                    uint32_t al3 = __float_as_uint(al[mt][1].y);
                    mma_tf32(acc[mt][nt], ah0, ah1, ah2, ah3, bh0, bh1);
                    mma_tf32(acc[mt][nt], ah0, ah1, ah2, ah3, bl0, bl1);
                    mma_tf32(acc[mt][nt], al0, al1, al2, al3, bh0, bh1);
                }
            }
        }
        __syncthreads();
        if (kt + 2 < 64) {
            gemm_load(kt + 2, st[buf], stu[buf], m0, n0, tid);
            CP_COMMIT();
        }
    }

    // epilogue: scatter into g_qkv[part][b][h][n][dh]
#pragma unroll
    for (int mt = 0; mt < 2; ++mt) {
#pragma unroll
        for (int nt = 0; nt < 8; ++nt) {
            int colg = n0 + warpn * 64 + nt * 8 + 2 * c;
            int part = colg >> 10;
            int pc   = colg & 1023;
            int h    = pc >> 6;
            int dh   = pc & 63;
#pragma unroll
            for (int rh = 0; rh < 2; ++rh) {
                int mg  = m0 + warpm * 32 + mt * 16 + g + rh * 8;
                int b   = mg >> 11;
                int seq = mg & 2047;
                float* dst = g_qkv + ((size_t)((part * BB + b) * HH + h) * NN + seq) * DH + dh;
                *(float2*)dst = make_float2(acc[mt][nt][rh * 2], acc[mt][nt][rh * 2 + 1]);
            }
        }
    }
}

// ---------------------------------------------------------------------------
// Kernel 2: causal flash attention, fp32 (unchanged from passing R5 kernel).
// ---------------------------------------------------------------------------
#define ATT_SMEM_BYTES (3 * 64 * 64 * 4)

__device__ __forceinline__ int swz(int row) {
    return (row & 15) ^ ((row >> 3) & 7);
}

__global__ __launch_bounds__(128, 4)
void attn_kernel(float* __restrict__ out)
{
    extern __shared__ float sma[];
    float* Qs = sma;            // [r][d], row-swizzled quads
    float* Ks = sma + 4096;     // K: [c][d] swizzled; later P: [r][k] swizzled
    float* Vs = sma + 8192;     // [k][d], natural

    const int qb = gridDim.x - 1 - blockIdx.x;   // heavy tiles first
    const int h  = blockIdx.y;
    const int b  = blockIdx.z;
    const int tid = threadIdx.x;
    const int tx = tid & 7;
    const int ty = tid >> 3;

    const float* Qg = g_qkv + (size_t)(((0 * BB + b) * HH + h)) * NN * DH + (size_t)qb * 64 * DH;
    const float* Kg = g_qkv + (size_t)(((1 * BB + b) * HH + h)) * NN * DH;
    const float* Vg = g_qkv + (size_t)(((2 * BB + b) * HH + h)) * NN * DH;

    int rq[4], swQ[4], swK[8];
#pragma unroll
    for (int i = 0; i < 4; ++i) { rq[i] = ty * 4 + i; swQ[i] = swz(rq[i]); }
#pragma unroll
    for (int j = 0; j < 8; ++j) swK[j] = swz(tx * 8 + j);

#pragma unroll
    for (int it = 0; it < 8; ++it) {
        int idx = it * 128 + tid;
        int r   = idx >> 4;
        int qd  = idx & 15;
        float4 v = *(const float4*)(Qg + (size_t)r * DH + qd * 4);
        v.x *= 0.125f; v.y *= 0.125f; v.z *= 0.125f; v.w *= 0.125f;
        *(float4*)&Qs[r * 64 + ((qd ^ swz(r)) << 2)] = v;
    }

    float o[4][8];
    float m_i[4], l_i[4];
#pragma unroll
    for (int i = 0; i < 4; ++i) {
        m_i[i] = -1e30f; l_i[i] = 0.0f;
#pragma unroll
        for (int j = 0; j < 8; ++j) o[i][j] = 0.0f;
    }

    const int nkt = qb + 1;
    for (int kt = 0; kt < nkt; ++kt) {
        __syncthreads();
#pragma unroll
        for (int it = 0; it < 8; ++it) {
            int idx = it * 128 + tid;
            int r   = idx >> 4;
            int qd  = idx & 15;
            float4 kv = *(const float4*)(Kg + (size_t)(kt * 64 + r) * DH + qd * 4);
            *(float4*)&Ks[r * 64 + ((qd ^ swz(r)) << 2)] = kv;
            float4 vv = *(const float4*)(Vg + (size_t)(kt * 64 + r) * DH + qd * 4);
            *(float4*)&Vs[r * 64 + qd * 4] = vv;
        }
        __syncthreads();

        float s[4][8];
#pragma unroll
        for (int i = 0; i < 4; ++i)
#pragma unroll
            for (int j = 0; j < 8; ++j) s[i][j] = 0.0f;

#pragma unroll 4
        for (int qd = 0; qd < 16; ++qd) {
            float4 qv[4];
#pragma unroll
            for (int i = 0; i < 4; ++i)
                qv[i] = *(const float4*)&Qs[rq[i] * 64 + ((qd ^ swQ[i]) << 2)];
#pragma unroll
            for (int half = 0; half < 2; ++half) {
                float4 kv[4];
#pragma unroll
                for (int jj = 0; jj < 4; ++jj) {
                    int j = half * 4 + jj;
                    kv[jj] = *(const float4*)&Ks[(tx * 8 + j) * 64 + ((qd ^ swK[j]) << 2)];
                }
#pragma unroll
                for (int i = 0; i < 4; ++i)
#pragma unroll
                    for (int jj = 0; jj < 4; ++jj) {
                        int j = half * 4 + jj;
                        s[i][j] = fmaf(qv[i].x, kv[jj].x, s[i][j]);
                        s[i][j] = fmaf(qv[i].y, kv[jj].y, s[i][j]);
                        s[i][j] = fmaf(qv[i].z, kv[jj].z, s[i][j]);
                        s[i][j] = fmaf(qv[i].w, kv[jj].w, s[i][j]);
                    }
            }
        }

        if (kt == qb) {
#pragma unroll
            for (int i = 0; i < 4; ++i)
#pragma unroll
                for (int j = 0; j < 8; ++j)
                    if ((tx * 8 + j) > (ty * 4 + i)) s[i][j] = -1e30f;
        }

        float corr[4];
#pragma unroll
        for (int i = 0; i < 4; ++i) {
            float mx = s[i][0];
#pragma unroll
            for (int j = 1; j < 8; ++j) mx = fmaxf(mx, s[i][j]);
            mx = fmaxf(mx, __shfl_xor_sync(0xffffffffu, mx, 1));
            mx = fmaxf(mx, __shfl_xor_sync(0xffffffffu, mx, 2));
            mx = fmaxf(mx, __shfl_xor_sync(0xffffffffu, mx, 4));
            float mnew = fmaxf(m_i[i], mx);
            corr[i] = __expf(m_i[i] - mnew);
            m_i[i] = mnew;
            float rs = 0.0f;
#pragma unroll
            for (int j = 0; j < 8; ++j) {
                float p = __expf(s[i][j] - mnew);
                s[i][j] = p;
                rs += p;
            }
            rs += __shfl_xor_sync(0xffffffffu, rs, 1);
            rs += __shfl_xor_sync(0xffffffffu, rs, 2);
            rs += __shfl_xor_sync(0xffffffffu, rs, 4);
            l_i[i] = l_i[i] * corr[i] + rs;
#pragma unroll
            for (int j = 0; j < 8; ++j) o[i][j] *= corr[i];
        }

        __syncthreads();
#pragma unroll
        for (int i = 0; i < 4; ++i) {
            *(float4*)&Ks[rq[i] * 64 + (((tx * 2)     ^ swQ[i]) << 2)] =
                make_float4(s[i][0], s[i][1], s[i][2], s[i][3]);
            *(float4*)&Ks[rq[i] * 64 + (((tx * 2 + 1) ^ swQ[i]) << 2)] =
                make_float4(s[i][4], s[i][5], s[i][6], s[i][7]);
        }
        __syncthreads();

#pragma unroll 4
        for (int kq = 0; kq < 16; ++kq) {
            float p[4][4];
#pragma unroll
            for (int i = 0; i < 4; ++i)
                *(float4*)p[i] = *(const float4*)&Ks[rq[i] * 64 + ((kq ^ swQ[i]) << 2)];
#pragma unroll
            for (int t = 0; t < 4; ++t) {
                int k = kq * 4 + t;
                float4 v0 = *(const float4*)&Vs[k * 64 + tx * 8];
                float4 v1 = *(const float4*)&Vs[k * 64 + tx * 8 + 4];
#pragma unroll
                for (int i = 0; i < 4; ++i) {
                    float pr = p[i][t];
                    o[i][0] = fmaf(pr, v0.x, o[i][0]);
                    o[i][1] = fmaf(pr, v0.y, o[i][1]);
                    o[i][2] = fmaf(pr, v0.z, o[i][2]);
                    o[i][3] = fmaf(pr, v0.w, o[i][3]);
                    o[i][4] = fmaf(pr, v1.x, o[i][4]);
                    o[i][5] = fmaf(pr, v1.y, o[i][5]);
                    o[i][6] = fmaf(pr, v1.z, o[i][6]);
                    o[i][7] = fmaf(pr, v1.w, o[i][7]);
                }
            }
        }
    }

#pragma unroll
    for (int i = 0; i < 4; ++i) {
        float inv = 1.0f / l_i[i];
        int qr = qb * 64 + ty * 4 + i;
        float4 r0 = make_float4(o[i][0] * inv, o[i][1] * inv, o[i][2] * inv, o[i][3] * inv);
        float4 r1 = make_float4(o[i][4] * inv, o[i][5] * inv, o[i][6] * inv, o[i][7] * inv);
        float* dst = out + (size_t)(b * NN + qr) * DD + h * DH + tx * 8;
        *(float4*)(dst)     = r0;
        *(float4*)(dst + 4) = r1;
    }
}

// ---------------------------------------------------------------------------
extern "C" void kernel_launch(void* const* d_in, const int* in_sizes, int n_in,
                              void* d_out, int out_size)
{
    const float* x = (const float*)d_in[0];   // [2,2048,1024] fp32
    const float* w = (const float*)d_in[1];   // [1024,3072] fp32
    float* out = (float*)d_out;               // [2,2048,1024] fp32
    (void)in_sizes; (void)n_in; (void)out_size;

    // tf32 hi/lo splits (+ W transpose), k pre-permuted for LDS.64 fragments
    prep_x<<<1024, 256>>>(x);
    prep_w<<<dim3(D3 / 32, DD / 32), dim3(32, 8)>>>(w);

    // tf32x3 QKV GEMM via mma.sync into per-head scratch
    cudaFuncSetAttribute(qkv_gemm_mma,
                         cudaFuncAttributeMaxDynamicSharedMemorySize,
                         GEMM_SMEM_TOTAL);
    qkv_gemm_mma<<<dim3(D3 / 128, MM / 128), 256, GEMM_SMEM_TOTAL>>>();

    // causal attention (fp32)
    cudaFuncSetAttribute(attn_kernel,
                         cudaFuncAttributeMaxDynamicSharedMemorySize,
                         ATT_SMEM_BYTES);
    dim3 g2(NN / 64, HH, BB);      // (32, 16, 2)
    attn_kernel<<<g2, 128, ATT_SMEM_BYTES>>>(out);
}

// round 8
// speedup vs baseline: 1.0478x; 1.0478x over previous
#include <cuda_runtime.h>
#include <cuda_bf16.h>
#include <cstdint>

// Problem constants
#define BB 2
#define NN 2048
#define HH 16
#define DH 64
#define DD 1024          // HH*DH
#define D3 3072          // 3*DD
#define MM 4096          // BB*NN

// Scratch: QKV laid out [part(q/k/v)][B][H][N][Dh]
__device__ float g_qkv[3u * BB * HH * NN * DH];
// tf32 hi/lo splits, k pre-permuted within each 8-block: [k0,k4,k1,k5,k2,k6,k3,k7]
__device__ float g_xhi[(size_t)MM * DD];     // [m][k']
__device__ float g_xlo[(size_t)MM * DD];
__device__ float g_whiT[(size_t)D3 * DD];    // [n][k']
__device__ float g_wloT[(size_t)D3 * DD];

// ---------------------------------------------------------------------------
// helpers
// ---------------------------------------------------------------------------
__device__ __forceinline__ float tf32_rna(float x) {
    uint32_t u;
    asm("cvt.rna.tf32.f32 %0, %1;" : "=r"(u) : "f"(x));
    return __uint_as_float(u);
}

#define CP_ASYNC16(dst_u32, gptr)                                              \
    asm volatile("cp.async.cg.shared.global [%0], [%1], 16;"                    \
                 :: "r"(dst_u32), "l"(__cvta_generic_to_global(gptr)))
#define CP_COMMIT() asm volatile("cp.async.commit_group;" ::: "memory")
#define CP_WAIT1()  asm volatile("cp.async.wait_group 1;" ::: "memory")
#define CP_WAIT0()  asm volatile("cp.async.wait_group 0;" ::: "memory")

__device__ __forceinline__ uint32_t smem_u32(const void* p) {
    uint32_t a;
    asm("{ .reg .u64 t; cvta.to.shared.u64 t, %1; cvt.u32.u64 %0, t; }"
        : "=r"(a) : "l"(p));
    return a;
}

// mma.sync m16n8k8 tf32: d += a * b
__device__ __forceinline__ void mma_tf32(float* d,
                                         uint32_t a0, uint32_t a1, uint32_t a2, uint32_t a3,
                                         uint32_t b0, uint32_t b1) {
    asm volatile(
        "mma.sync.aligned.m16n8k8.row.col.f32.tf32.tf32.f32 "
        "{%0,%1,%2,%3}, {%4,%5,%6,%7}, {%8,%9}, {%0,%1,%2,%3};"
        : "+f"(d[0]), "+f"(d[1]), "+f"(d[2]), "+f"(d[3])
        : "r"(a0), "r"(a1), "r"(a2), "r"(a3), "r"(b0), "r"(b1));
}

// ---------------------------------------------------------------------------
// Prep kernels: tf32 hi/lo split, k-permutation (+ transpose for W)
// ---------------------------------------------------------------------------
__global__ __launch_bounds__(256)
void prep_x(const float* __restrict__ X)
{
    const size_t n8 = (size_t)MM * DD / 8;
    for (size_t i = blockIdx.x * 256 + threadIdx.x; i < n8; i += (size_t)gridDim.x * 256) {
        const float* src = X + i * 8;
        float4 v0 = *(const float4*)(src);
        float4 v1 = *(const float4*)(src + 4);
        float s[8] = {v0.x, v0.y, v0.z, v0.w, v1.x, v1.y, v1.z, v1.w};
        float hi[8], lo[8];
#pragma unroll
        for (int k = 0; k < 8; ++k) {
            hi[k] = tf32_rna(s[k]);
            lo[k] = tf32_rna(s[k] - hi[k]);
        }
        // dest order: k0,k4,k1,k5,k2,k6,k3,k7
        float4 h0 = make_float4(hi[0], hi[4], hi[1], hi[5]);
        float4 h1 = make_float4(hi[2], hi[6], hi[3], hi[7]);
        float4 l0 = make_float4(lo[0], lo[4], lo[1], lo[5]);
        float4 l1 = make_float4(lo[2], lo[6], lo[3], lo[7]);
        *(float4*)(g_xhi + i * 8)     = h0;
        *(float4*)(g_xhi + i * 8 + 4) = h1;
        *(float4*)(g_xlo + i * 8)     = l0;
        *(float4*)(g_xlo + i * 8 + 4) = l1;
    }
}

__device__ __forceinline__ int kperm8(int k) {
    return (k & ~7) | (((k & 3) << 1) | ((k >> 2) & 1));
}

__global__ __launch_bounds__(256)
void prep_w(const float* __restrict__ W)
{
    __shared__ float t[32][33];
    const int n0 = blockIdx.x * 32;
    const int k0 = blockIdx.y * 32;
    const int tx = threadIdx.x, ty = threadIdx.y;   // (32, 8)
#pragma unroll
    for (int rr = 0; rr < 32; rr += 8)
        t[ty + rr][tx] = W[(size_t)(k0 + ty + rr) * D3 + n0 + tx];   // t[kk][nn]
    __syncthreads();
#pragma unroll
    for (int rr = 0; rr < 32; rr += 8) {
        float v  = t[tx][ty + rr];          // kk = tx, nn = ty+rr
        float hi = tf32_rna(v);
        float lo = tf32_rna(v - hi);
        size_t base = (size_t)(n0 + ty + rr) * DD + k0 + kperm8(tx);
        g_whiT[base] = hi;
        g_wloT[base] = lo;
    }
}

// ---------------------------------------------------------------------------
// tf32x3 QKV GEMM via mma.sync m16n8k8.
// CTA 128x128, 256 threads (warps 4m x 2n, warp tile 32x64), k-chunk 16,
// cp.async double buffer. Row stride 20 floats (pad 16->20) makes the
// fragment LDS.64 pattern tile the 16 bank-pairs exactly 2-deep
// (the LDS.64 phase minimum) instead of 4-way conflicting.
// ---------------------------------------------------------------------------
#define ROWW 20                 // padded row stride in floats
#define OAHI 0
#define OALO 2560
#define OBHI 5120
#define OBLO 7680
#define ST_FLOATS 10240         // 40KB per stage in floats
#define GEMM_SMEM_TOTAL (2 * ST_FLOATS * 4)

__device__ __forceinline__ void gemm_load(int kt, uint32_t st_u32,
                                          int m0, int n0, int tid)
{
    const int k0 = kt * 16;
    // each matrix-half: 128 rows x 4 chunks of 16B; 256 threads x 2
#pragma unroll
    for (int it = 0; it < 2; ++it) {
        int j   = it * 256 + tid;
        int row = j >> 2;
        int q   = (j & 3) * 4;
        uint32_t doff = (uint32_t)(row * ROWW + q) * 4;
        CP_ASYNC16(st_u32 + OAHI * 4 + doff, g_xhi  + (size_t)(m0 + row) * DD + k0 + q);
        CP_ASYNC16(st_u32 + OALO * 4 + doff, g_xlo  + (size_t)(m0 + row) * DD + k0 + q);
        CP_ASYNC16(st_u32 + OBHI * 4 + doff, g_whiT + (size_t)(n0 + row) * DD + k0 + q);
        CP_ASYNC16(st_u32 + OBLO * 4 + doff, g_wloT + (size_t)(n0 + row) * DD + k0 + q);
    }
}

__global__ __launch_bounds__(256, 2)
void qkv_gemm_mma()
{
    extern __shared__ float sm[];
    const int tid   = threadIdx.x;
    const int wid   = tid >> 5;
    const int lane  = tid & 31;
    const int warpm = wid & 3;        // 4 warps over m (32 rows each)
    const int warpn = wid >> 2;       // 2 warps over n (64 cols each)
    const int c     = lane & 3;
    const int g     = lane >> 2;
    const int n0    = blockIdx.x * 128;
    const int m0    = blockIdx.y * 128;

    float* st[2] = {sm, sm + ST_FLOATS};
    uint32_t stu[2] = {smem_u32(sm), smem_u32(sm + ST_FLOATS)};

    float acc[2][8][4];
#pragma unroll
    for (int mt = 0; mt < 2; ++mt)
#pragma unroll
        for (int nt = 0; nt < 8; ++nt)
#pragma unroll
            for (int v = 0; v < 4; ++v) acc[mt][nt][v] = 0.0f;

    gemm_load(0, stu[0], m0, n0, tid); CP_COMMIT();
    gemm_load(1, stu[1], m0, n0, tid); CP_COMMIT();

    for (int kt = 0; kt < 64; ++kt) {
        const int buf = kt & 1;
        if (kt < 62) { CP_WAIT1(); } else { CP_WAIT0(); }
        __syncthreads();

        const float* S = st[buf];
#pragma unroll
        for (int ks = 0; ks < 2; ++ks) {
            const int kc = ks * 8 + 2 * c;
            float2 ah[2][2], al[2][2];
#pragma unroll
            for (int mt = 0; mt < 2; ++mt) {
                int rbase = warpm * 32 + mt * 16 + g;
                ah[mt][0] = *(const float2*)&S[OAHI + rbase * ROWW + kc];
                ah[mt][1] = *(const float2*)&S[OAHI + (rbase + 8) * ROWW + kc];
                al[mt][0] = *(const float2*)&S[OALO + rbase * ROWW + kc];
                al[mt][1] = *(const float2*)&S[OALO + (rbase + 8) * ROWW + kc];
            }
#pragma unroll
            for (int nt = 0; nt < 8; ++nt) {
                int nb = (warpn * 64 + nt * 8 + g) * ROWW + kc;
                float2 bh = *(const float2*)&S[OBHI + nb];
                float2 bl = *(const float2*)&S[OBLO + nb];
                uint32_t bh0 = __float_as_uint(bh.x), bh1 = __float_as_uint(bh.y);
                uint32_t bl0 = __float_as_uint(bl.x), bl1 = __float_as_uint(bl.y);
#pragma unroll
                for (int mt = 0; mt < 2; ++mt) {
                    uint32_t ah0 = __float_as_uint(ah[mt][0].x);
                    uint32_t ah1 = __float_as_uint(ah[mt][1].x);
                    uint32_t ah2 = __float_as_uint(ah[mt][0].y);
                    uint32_t ah3 = __float_as_uint(ah[mt][1].y);
                    uint32_t al0 = __float_as_uint(al[mt][0].x);
                    uint32_t al1 = __float_as_uint(al[mt][1].x);
                    uint32_t al2 = __float_as_uint(al[mt][0].y);
                    uint32_t al3 = __float_as_uint(al[mt][1].y);
                    mma_tf32(acc[mt][nt], ah0, ah1, ah2, ah3, bh0, bh1);
                    mma_tf32(acc[mt][nt], ah0, ah1, ah2, ah3, bl0, bl1);
                    mma_tf32(acc[mt][nt], al0, al1, al2, al3, bh0, bh1);
                }
            }
        }
        __syncthreads();
        if (kt + 2 < 64) {
            gemm_load(kt + 2, stu[buf], m0, n0, tid);
            CP_COMMIT();
        }
    }

    // epilogue: scatter into g_qkv[part][b][h][n][dh]
#pragma unroll
    for (int mt = 0; mt < 2; ++mt) {
#pragma unroll
        for (int nt = 0; nt < 8; ++nt) {
            int colg = n0 + warpn * 64 + nt * 8 + 2 * c;
            int part = colg >> 10;
            int pc   = colg & 1023;
            int h    = pc >> 6;
            int dh   = pc & 63;
#pragma unroll
            for (int rh = 0; rh < 2; ++rh) {
                int mg  = m0 + warpm * 32 + mt * 16 + g + rh * 8;
                int b   = mg >> 11;
                int seq = mg & 2047;
                float* dst = g_qkv + ((size_t)((part * BB + b) * HH + h) * NN + seq) * DH + dh;
                *(float2*)dst = make_float2(acc[mt][nt][rh * 2], acc[mt][nt][rh * 2 + 1]);
            }
        }
    }
}

// ---------------------------------------------------------------------------
// Kernel 2: causal flash attention, fp32 (unchanged from passing R5 kernel).
// ---------------------------------------------------------------------------
#define ATT_SMEM_BYTES (3 * 64 * 64 * 4)

__device__ __forceinline__ int swz(int row) {
    return (row & 15) ^ ((row >> 3) & 7);
}

__global__ __launch_bounds__(128, 4)
void attn_kernel(float* __restrict__ out)
{
    extern __shared__ float sma[];
    float* Qs = sma;            // [r][d], row-swizzled quads
    float* Ks = sma + 4096;     // K: [c][d] swizzled; later P: [r][k] swizzled
    float* Vs = sma + 8192;     // [k][d], natural

    const int qb = gridDim.x - 1 - blockIdx.x;   // heavy tiles first
    const int h  = blockIdx.y;
    const int b  = blockIdx.z;
    const int tid = threadIdx.x;
    const int tx = tid & 7;
    const int ty = tid >> 3;

    const float* Qg = g_qkv + (size_t)(((0 * BB + b) * HH + h)) * NN * DH + (size_t)qb * 64 * DH;
    const float* Kg = g_qkv + (size_t)(((1 * BB + b) * HH + h)) * NN * DH;
    const float* Vg = g_qkv + (size_t)(((2 * BB + b) * HH + h)) * NN * DH;

    int rq[4], swQ[4], swK[8];
#pragma unroll
    for (int i = 0; i < 4; ++i) { rq[i] = ty * 4 + i; swQ[i] = swz(rq[i]); }
#pragma unroll
    for (int j = 0; j < 8; ++j) swK[j] = swz(tx * 8 + j);

#pragma unroll
    for (int it = 0; it < 8; ++it) {
        int idx = it * 128 + tid;
        int r   = idx >> 4;
        int qd  = idx & 15;
        float4 v = *(const float4*)(Qg + (size_t)r * DH + qd * 4);
        v.x *= 0.125f; v.y *= 0.125f; v.z *= 0.125f; v.w *= 0.125f;
        *(float4*)&Qs[r * 64 + ((qd ^ swz(r)) << 2)] = v;
    }

    float o[4][8];
    float m_i[4], l_i[4];
#pragma unroll
    for (int i = 0; i < 4; ++i) {
        m_i[i] = -1e30f; l_i[i] = 0.0f;
#pragma unroll
        for (int j = 0; j < 8; ++j) o[i][j] = 0.0f;
    }

    const int nkt = qb + 1;
    for (int kt = 0; kt < nkt; ++kt) {
        __syncthreads();
#pragma unroll
        for (int it = 0; it < 8; ++it) {
            int idx = it * 128 + tid;
            int r   = idx >> 4;
            int qd  = idx & 15;
            float4 kv = *(const float4*)(Kg + (size_t)(kt * 64 + r) * DH + qd * 4);
            *(float4*)&Ks[r * 64 + ((qd ^ swz(r)) << 2)] = kv;
            float4 vv = *(const float4*)(Vg + (size_t)(kt * 64 + r) * DH + qd * 4);
            *(float4*)&Vs[r * 64 + qd * 4] = vv;
        }
        __syncthreads();

        float s[4][8];
#pragma unroll
        for (int i = 0; i < 4; ++i)
#pragma unroll
            for (int j = 0; j < 8; ++j) s[i][j] = 0.0f;

#pragma unroll 4
        for (int qd = 0; qd < 16; ++qd) {
            float4 qv[4];
#pragma unroll
            for (int i = 0; i < 4; ++i)
                qv[i] = *(const float4*)&Qs[rq[i] * 64 + ((qd ^ swQ[i]) << 2)];
#pragma unroll
            for (int half = 0; half < 2; ++half) {
                float4 kv[4];
#pragma unroll
                for (int jj = 0; jj < 4; ++jj) {
                    int j = half * 4 + jj;
                    kv[jj] = *(const float4*)&Ks[(tx * 8 + j) * 64 + ((qd ^ swK[j]) << 2)];
                }
#pragma unroll
                for (int i = 0; i < 4; ++i)
#pragma unroll
                    for (int jj = 0; jj < 4; ++jj) {
                        int j = half * 4 + jj;
                        s[i][j] = fmaf(qv[i].x, kv[jj].x, s[i][j]);
                        s[i][j] = fmaf(qv[i].y, kv[jj].y, s[i][j]);
                        s[i][j] = fmaf(qv[i].z, kv[jj].z, s[i][j]);
                        s[i][j] = fmaf(qv[i].w, kv[jj].w, s[i][j]);
                    }
            }
        }

        if (kt == qb) {
#pragma unroll
            for (int i = 0; i < 4; ++i)
#pragma unroll
                for (int j = 0; j < 8; ++j)
                    if ((tx * 8 + j) > (ty * 4 + i)) s[i][j] = -1e30f;
        }

        float corr[4];
#pragma unroll
        for (int i = 0; i < 4; ++i) {
            float mx = s[i][0];
#pragma unroll
            for (int j = 1; j < 8; ++j) mx = fmaxf(mx, s[i][j]);
            mx = fmaxf(mx, __shfl_xor_sync(0xffffffffu, mx, 1));
            mx = fmaxf(mx, __shfl_xor_sync(0xffffffffu, mx, 2));
            mx = fmaxf(mx, __shfl_xor_sync(0xffffffffu, mx, 4));
            float mnew = fmaxf(m_i[i], mx);
            corr[i] = __expf(m_i[i] - mnew);
            m_i[i] = mnew;
            float rs = 0.0f;
#pragma unroll
            for (int j = 0; j < 8; ++j) {
                float p = __expf(s[i][j] - mnew);
                s[i][j] = p;
                rs += p;
            }
            rs += __shfl_xor_sync(0xffffffffu, rs, 1);
            rs += __shfl_xor_sync(0xffffffffu, rs, 2);
            rs += __shfl_xor_sync(0xffffffffu, rs, 4);
            l_i[i] = l_i[i] * corr[i] + rs;
#pragma unroll
            for (int j = 0; j < 8; ++j) o[i][j] *= corr[i];
        }

        __syncthreads();
#pragma unroll
        for (int i = 0; i < 4; ++i) {
            *(float4*)&Ks[rq[i] * 64 + (((tx * 2)     ^ swQ[i]) << 2)] =
                make_float4(s[i][0], s[i][1], s[i][2], s[i][3]);
            *(float4*)&Ks[rq[i] * 64 + (((tx * 2 + 1) ^ swQ[i]) << 2)] =
                make_float4(s[i][4], s[i][5], s[i][6], s[i][7]);
        }
        __syncthreads();

#pragma unroll 4
        for (int kq = 0; kq < 16; ++kq) {
            float p[4][4];
#pragma unroll
            for (int i = 0; i < 4; ++i)
                *(float4*)p[i] = *(const float4*)&Ks[rq[i] * 64 + ((kq ^ swQ[i]) << 2)];
#pragma unroll
            for (int t = 0; t < 4; ++t) {
                int k = kq * 4 + t;
                float4 v0 = *(const float4*)&Vs[k * 64 + tx * 8];
                float4 v1 = *(const float4*)&Vs[k * 64 + tx * 8 + 4];
#pragma unroll
                for (int i = 0; i < 4; ++i) {
                    float pr = p[i][t];
                    o[i][0] = fmaf(pr, v0.x, o[i][0]);
                    o[i][1] = fmaf(pr, v0.y, o[i][1]);
                    o[i][2] = fmaf(pr, v0.z, o[i][2]);
                    o[i][3] = fmaf(pr, v0.w, o[i][3]);
                    o[i][4] = fmaf(pr, v1.x, o[i][4]);
                    o[i][5] = fmaf(pr, v1.y, o[i][5]);
                    o[i][6] = fmaf(pr, v1.z, o[i][6]);
                    o[i][7] = fmaf(pr, v1.w, o[i][7]);
                }
            }
        }
    }

#pragma unroll
    for (int i = 0; i < 4; ++i) {
        float inv = 1.0f / l_i[i];
        int qr = qb * 64 + ty * 4 + i;
        float4 r0 = make_float4(o[i][0] * inv, o[i][1] * inv, o[i][2] * inv, o[i][3] * inv);
        float4 r1 = make_float4(o[i][4] * inv, o[i][5] * inv, o[i][6] * inv, o[i][7] * inv);
        float* dst = out + (size_t)(b * NN + qr) * DD + h * DH + tx * 8;
        *(float4*)(dst)     = r0;
        *(float4*)(dst + 4) = r1;
    }
}

// ---------------------------------------------------------------------------
extern "C" void kernel_launch(void* const* d_in, const int* in_sizes, int n_in,
                              void* d_out, int out_size)
{
    const float* x = (const float*)d_in[0];   // [2,2048,1024] fp32
    const float* w = (const float*)d_in[1];   // [1024,3072] fp32
    float* out = (float*)d_out;               // [2,2048,1024] fp32
    (void)in_sizes; (void)n_in; (void)out_size;

    // tf32 hi/lo splits (+ W transpose), k pre-permuted for LDS.64 fragments
    prep_x<<<1024, 256>>>(x);
    prep_w<<<dim3(D3 / 32, DD / 32), dim3(32, 8)>>>(w);

    // tf32x3 QKV GEMM via mma.sync into per-head scratch
    cudaFuncSetAttribute(qkv_gemm_mma,
                         cudaFuncAttributeMaxDynamicSharedMemorySize,
                         GEMM_SMEM_TOTAL);
    qkv_gemm_mma<<<dim3(D3 / 128, MM / 128), 256, GEMM_SMEM_TOTAL>>>();

    // causal attention (fp32)
    cudaFuncSetAttribute(attn_kernel,
                         cudaFuncAttributeMaxDynamicSharedMemorySize,
                         ATT_SMEM_BYTES);
    dim3 g2(NN / 64, HH, BB);      // (32, 16, 2)
    attn_kernel<<<g2, 128, ATT_SMEM_BYTES>>>(out);
}

// round 9
// speedup vs baseline: 1.3320x; 1.2712x over previous
#include <cuda_runtime.h>
#include <cuda_bf16.h>
#include <cstdint>

// Problem constants
#define BB 2
#define NN 2048
#define HH 16
#define DH 64
#define DD 1024          // HH*DH
#define D3 3072          // 3*DD
#define MM 4096          // BB*NN

// Scratch: QKV laid out [part(q/k/v)][B][H][N][Dh]
__device__ float g_qkv[3u * BB * HH * NN * DH];
// bf16 hi/lo splits, b32-pair order within each k16 block: [p0,p4,p1,p5,p2,p6,p3,p7]
__device__ __nv_bfloat16 g_xhi[(size_t)MM * DD];     // [m][k']
__device__ __nv_bfloat16 g_xlo[(size_t)MM * DD];
__device__ __nv_bfloat16 g_whiT[(size_t)D3 * DD];    // [n][k']
__device__ __nv_bfloat16 g_wloT[(size_t)D3 * DD];

// ---------------------------------------------------------------------------
// helpers
// ---------------------------------------------------------------------------
#define CP_ASYNC16(dst_u32, gptr)                                              \
    asm volatile("cp.async.cg.shared.global [%0], [%1], 16;"                    \
                 :: "r"(dst_u32), "l"(__cvta_generic_to_global(gptr)))
#define CP_COMMIT() asm volatile("cp.async.commit_group;" ::: "memory")
#define CP_WAIT1()  asm volatile("cp.async.wait_group 1;" ::: "memory")
#define CP_WAIT0()  asm volatile("cp.async.wait_group 0;" ::: "memory")

__device__ __forceinline__ uint32_t smem_u32(const void* p) {
    uint32_t a;
    asm("{ .reg .u64 t; cvta.to.shared.u64 t, %1; cvt.u32.u64 %0, t; }"
        : "=r"(a) : "l"(p));
    return a;
}

// mma.sync m16n8k16 bf16: d += a * b  (f32 accumulate)
__device__ __forceinline__ void mma_bf16(float* d,
                                         uint32_t a0, uint32_t a1, uint32_t a2, uint32_t a3,
                                         uint32_t b0, uint32_t b1) {
    asm volatile(
        "mma.sync.aligned.m16n8k16.row.col.f32.bf16.bf16.f32 "
        "{%0,%1,%2,%3}, {%4,%5,%6,%7}, {%8,%9}, {%0,%1,%2,%3};"
        : "+f"(d[0]), "+f"(d[1]), "+f"(d[2]), "+f"(d[3])
        : "r"(a0), "r"(a1), "r"(a2), "r"(a3), "r"(b0), "r"(b1));
}

__device__ __forceinline__ uint32_t pack_bf16(float x0, float x1) {
    __nv_bfloat16 h0 = __float2bfloat16_rn(x0);
    __nv_bfloat16 h1 = __float2bfloat16_rn(x1);
    return (uint32_t)__bfloat16_as_ushort(h0) |
           ((uint32_t)__bfloat16_as_ushort(h1) << 16);
}

// ---------------------------------------------------------------------------
// Prep kernels: bf16 hi/lo split, pair-permutation (+ transpose for W)
// ---------------------------------------------------------------------------
__global__ __launch_bounds__(256)
void prep_x(const float* __restrict__ X)
{
    const size_t n16 = (size_t)MM * DD / 16;
    for (size_t i = (size_t)blockIdx.x * 256 + threadIdx.x; i < n16;
         i += (size_t)gridDim.x * 256) {
        const float* src = X + i * 16;
        float s[16];
        *(float4*)(s)      = ((const float4*)src)[0];
        *(float4*)(s + 4)  = ((const float4*)src)[1];
        *(float4*)(s + 8)  = ((const float4*)src)[2];
        *(float4*)(s + 12) = ((const float4*)src)[3];
        float hi[16], lo[16];
#pragma unroll
        for (int k = 0; k < 16; ++k) {
            __nv_bfloat16 h = __float2bfloat16_rn(s[k]);
            hi[k] = __bfloat162float(h);
            lo[k] = s[k] - hi[k];
        }
        // dest pair order: p0,p4,p1,p5,p2,p6,p3,p7
        const int pp[8] = {0, 4, 1, 5, 2, 6, 3, 7};
        uint32_t ph[8], pl[8];
#pragma unroll
        for (int d = 0; d < 8; ++d) {
            int p = pp[d];
            ph[d] = pack_bf16(hi[2 * p], hi[2 * p + 1]);
            pl[d] = pack_bf16(lo[2 * p], lo[2 * p + 1]);
        }
        uint32_t* dh = (uint32_t*)g_xhi + i * 8;
        uint32_t* dl = (uint32_t*)g_xlo + i * 8;
        *(uint4*)(dh)     = make_uint4(ph[0], ph[1], ph[2], ph[3]);
        *(uint4*)(dh + 4) = make_uint4(ph[4], ph[5], ph[6], ph[7]);
        *(uint4*)(dl)     = make_uint4(pl[0], pl[1], pl[2], pl[3]);
        *(uint4*)(dl + 4) = make_uint4(pl[4], pl[5], pl[6], pl[7]);
    }
}

__device__ __forceinline__ int kperm16(int k) {
    // dest index of source k within its 16-block after pair permutation
    int p = (k >> 1) & 7;
    int d = ((p & 3) << 1) | (p >> 2);
    return (k & ~15) | (d * 2) | (k & 1);
}

__global__ __launch_bounds__(256)
void prep_w(const float* __restrict__ W)
{
    __shared__ float t[32][33];
    const int n0 = blockIdx.x * 32;
    const int k0 = blockIdx.y * 32;
    const int tx = threadIdx.x, ty = threadIdx.y;   // (32, 8)
#pragma unroll
    for (int rr = 0; rr < 32; rr += 8)
        t[ty + rr][tx] = W[(size_t)(k0 + ty + rr) * D3 + n0 + tx];   // t[kk][nn]
    __syncthreads();
#pragma unroll
    for (int rr = 0; rr < 32; rr += 8) {
        float v  = t[tx][ty + rr];          // kk = tx, nn = ty+rr
        __nv_bfloat16 h = __float2bfloat16_rn(v);
        float hf = __bfloat162float(h);
        __nv_bfloat16 l = __float2bfloat16_rn(v - hf);
        size_t base = (size_t)(n0 + ty + rr) * DD + k0 + kperm16(tx);
        g_whiT[base] = h;
        g_wloT[base] = l;
    }
}

// ---------------------------------------------------------------------------
// bf16x3 QKV GEMM via mma.sync m16n8k16.
// CTA 128x128, 256 threads (warps 4m x 2n, warp tile 32x64), k-chunk 32,
// cp.async double buffer. Stage rows padded to 20 b32 (16 data) so fragment
// LDS.64s tile the 16 bank-pairs exactly 2-deep (phase minimum).
// ---------------------------------------------------------------------------
#define ROWW 20                 // padded row stride in b32 units (32 bf16 data)
#define OAHI 0
#define OALO 2560
#define OBHI 5120
#define OBLO 7680
#define ST_B32 10240            // 40KB per stage
#define GEMM_SMEM_TOTAL (2 * ST_B32 * 4)

__device__ __forceinline__ void gemm_load(int kt, uint32_t st_u32,
                                          int m0, int n0, int tid)
{
    const int k0 = kt * 32;     // bf16 element offset
    // each matrix-half: 128 rows x 4 chunks of 16B; 256 threads x 2
#pragma unroll
    for (int it = 0; it < 2; ++it) {
        int j   = it * 256 + tid;
        int row = j >> 2;
        int q   = (j & 3);                        // 16B chunk (8 bf16)
        uint32_t doff = (uint32_t)(row * ROWW + q * 4) * 4;
        CP_ASYNC16(st_u32 + OAHI * 4 + doff, g_xhi  + (size_t)(m0 + row) * DD + k0 + q * 8);
        CP_ASYNC16(st_u32 + OALO * 4 + doff, g_xlo  + (size_t)(m0 + row) * DD + k0 + q * 8);
        CP_ASYNC16(st_u32 + OBHI * 4 + doff, g_whiT + (size_t)(n0 + row) * DD + k0 + q * 8);
        CP_ASYNC16(st_u32 + OBLO * 4 + doff, g_wloT + (size_t)(n0 + row) * DD + k0 + q * 8);
    }
}

__global__ __launch_bounds__(256, 2)
void qkv_gemm_mma()
{
    extern __shared__ float sm[];
    const int tid   = threadIdx.x;
    const int wid   = tid >> 5;
    const int lane  = tid & 31;
    const int warpm = wid & 3;        // 4 warps over m (32 rows each)
    const int warpn = wid >> 2;       // 2 warps over n (64 cols each)
    const int c     = lane & 3;
    const int g     = lane >> 2;
    const int n0    = blockIdx.x * 128;
    const int m0    = blockIdx.y * 128;

    const uint32_t* st[2] = {(const uint32_t*)sm, (const uint32_t*)sm + ST_B32};
    uint32_t stu[2] = {smem_u32(sm), smem_u32(sm + ST_B32)};

    float acc[2][8][4];
#pragma unroll
    for (int mt = 0; mt < 2; ++mt)
#pragma unroll
        for (int nt = 0; nt < 8; ++nt)
#pragma unroll
            for (int v = 0; v < 4; ++v) acc[mt][nt][v] = 0.0f;

    gemm_load(0, stu[0], m0, n0, tid); CP_COMMIT();
    gemm_load(1, stu[1], m0, n0, tid); CP_COMMIT();

    for (int kt = 0; kt < 32; ++kt) {
        const int buf = kt & 1;
        if (kt < 30) { CP_WAIT1(); } else { CP_WAIT0(); }
        __syncthreads();

        const uint32_t* S = st[buf];
#pragma unroll
        for (int ks = 0; ks < 2; ++ks) {
            const int kc = ks * 8 + 2 * c;        // b32 index within row
            uint2 ah[2][2], al[2][2];             // [mt][rowhalf] -> (pair c, pair c+4)
#pragma unroll
            for (int mt = 0; mt < 2; ++mt) {
                int rbase = warpm * 32 + mt * 16 + g;
                ah[mt][0] = *(const uint2*)&S[OAHI + rbase * ROWW + kc];
                ah[mt][1] = *(const uint2*)&S[OAHI + (rbase + 8) * ROWW + kc];
                al[mt][0] = *(const uint2*)&S[OALO + rbase * ROWW + kc];
                al[mt][1] = *(const uint2*)&S[OALO + (rbase + 8) * ROWW + kc];
            }
#pragma unroll
            for (int nt = 0; nt < 8; ++nt) {
                int nb = (warpn * 64 + nt * 8 + g) * ROWW + kc;
                uint2 bh = *(const uint2*)&S[OBHI + nb];
                uint2 bl = *(const uint2*)&S[OBLO + nb];
#pragma unroll
                for (int mt = 0; mt < 2; ++mt) {
                    mma_bf16(acc[mt][nt], ah[mt][0].x, ah[mt][1].x,
                             ah[mt][0].y, ah[mt][1].y, bh.x, bh.y);
                    mma_bf16(acc[mt][nt], ah[mt][0].x, ah[mt][1].x,
                             ah[mt][0].y, ah[mt][1].y, bl.x, bl.y);
                    mma_bf16(acc[mt][nt], al[mt][0].x, al[mt][1].x,
                             al[mt][0].y, al[mt][1].y, bh.x, bh.y);
                }
            }
        }
        __syncthreads();
        if (kt + 2 < 32) {
            gemm_load(kt + 2, stu[buf], m0, n0, tid);
            CP_COMMIT();
        }
    }

    // epilogue: scatter into g_qkv[part][b][h][n][dh]
#pragma unroll
    for (int mt = 0; mt < 2; ++mt) {
#pragma unroll
        for (int nt = 0; nt < 8; ++nt) {
            int colg = n0 + warpn * 64 + nt * 8 + 2 * c;
            int part = colg >> 10;
            int pc   = colg & 1023;
            int h    = pc >> 6;
            int dh   = pc & 63;
#pragma unroll
            for (int rh = 0; rh < 2; ++rh) {
                int mg  = m0 + warpm * 32 + mt * 16 + g + rh * 8;
                int b   = mg >> 11;
                int seq = mg & 2047;
                float* dst = g_qkv + ((size_t)((part * BB + b) * HH + h) * NN + seq) * DH + dh;
                *(float2*)dst = make_float2(acc[mt][nt][rh * 2], acc[mt][nt][rh * 2 + 1]);
            }
        }
    }
}

// ---------------------------------------------------------------------------
// Kernel 2: causal flash attention, fp32 (unchanged from passing R5 kernel).
// ---------------------------------------------------------------------------
#define ATT_SMEM_BYTES (3 * 64 * 64 * 4)

__device__ __forceinline__ int swz(int row) {
    return (row & 15) ^ ((row >> 3) & 7);
}

__global__ __launch_bounds__(128, 4)
void attn_kernel(float* __restrict__ out)
{
    extern __shared__ float sma[];
    float* Qs = sma;            // [r][d], row-swizzled quads
    float* Ks = sma + 4096;     // K: [c][d] swizzled; later P: [r][k] swizzled
    float* Vs = sma + 8192;     // [k][d], natural

    const int qb = gridDim.x - 1 - blockIdx.x;   // heavy tiles first
    const int h  = blockIdx.y;
    const int b  = blockIdx.z;
    const int tid = threadIdx.x;
    const int tx = tid & 7;
    const int ty = tid >> 3;

    const float* Qg = g_qkv + (size_t)(((0 * BB + b) * HH + h)) * NN * DH + (size_t)qb * 64 * DH;
    const float* Kg = g_qkv + (size_t)(((1 * BB + b) * HH + h)) * NN * DH;
    const float* Vg = g_qkv + (size_t)(((2 * BB + b) * HH + h)) * NN * DH;

    int rq[4], swQ[4], swK[8];
#pragma unroll
    for (int i = 0; i < 4; ++i) { rq[i] = ty * 4 + i; swQ[i] = swz(rq[i]); }
#pragma unroll
    for (int j = 0; j < 8; ++j) swK[j] = swz(tx * 8 + j);

#pragma unroll
    for (int it = 0; it < 8; ++it) {
        int idx = it * 128 + tid;
        int r   = idx >> 4;
        int qd  = idx & 15;
        float4 v = *(const float4*)(Qg + (size_t)r * DH + qd * 4);
        v.x *= 0.125f; v.y *= 0.125f; v.z *= 0.125f; v.w *= 0.125f;
        *(float4*)&Qs[r * 64 + ((qd ^ swz(r)) << 2)] = v;
    }

    float o[4][8];
    float m_i[4], l_i[4];
#pragma unroll
    for (int i = 0; i < 4; ++i) {
        m_i[i] = -1e30f; l_i[i] = 0.0f;
#pragma unroll
        for (int j = 0; j < 8; ++j) o[i][j] = 0.0f;
    }

    const int nkt = qb + 1;
    for (int kt = 0; kt < nkt; ++kt) {
        __syncthreads();
#pragma unroll
        for (int it = 0; it < 8; ++it) {
            int idx = it * 128 + tid;
            int r   = idx >> 4;
            int qd  = idx & 15;
            float4 kv = *(const float4*)(Kg + (size_t)(kt * 64 + r) * DH + qd * 4);
            *(float4*)&Ks[r * 64 + ((qd ^ swz(r)) << 2)] = kv;
            float4 vv = *(const float4*)(Vg + (size_t)(kt * 64 + r) * DH + qd * 4);
            *(float4*)&Vs[r * 64 + qd * 4] = vv;
        }
        __syncthreads();

        float s[4][8];
#pragma unroll
        for (int i = 0; i < 4; ++i)
#pragma unroll
            for (int j = 0; j < 8; ++j) s[i][j] = 0.0f;

#pragma unroll 4
        for (int qd = 0; qd < 16; ++qd) {
            float4 qv[4];
#pragma unroll
            for (int i = 0; i < 4; ++i)
                qv[i] = *(const float4*)&Qs[rq[i] * 64 + ((qd ^ swQ[i]) << 2)];
#pragma unroll
            for (int half = 0; half < 2; ++half) {
                float4 kv[4];
#pragma unroll
                for (int jj = 0; jj < 4; ++jj) {
                    int j = half * 4 + jj;
                    kv[jj] = *(const float4*)&Ks[(tx * 8 + j) * 64 + ((qd ^ swK[j]) << 2)];
                }
#pragma unroll
                for (int i = 0; i < 4; ++i)
#pragma unroll
                    for (int jj = 0; jj < 4; ++jj) {
                        int j = half * 4 + jj;
                        s[i][j] = fmaf(qv[i].x, kv[jj].x, s[i][j]);
                        s[i][j] = fmaf(qv[i].y, kv[jj].y, s[i][j]);
                        s[i][j] = fmaf(qv[i].z, kv[jj].z, s[i][j]);
                        s[i][j] = fmaf(qv[i].w, kv[jj].w, s[i][j]);
                    }
            }
        }

        if (kt == qb) {
#pragma unroll
            for (int i = 0; i < 4; ++i)
#pragma unroll
                for (int j = 0; j < 8; ++j)
                    if ((tx * 8 + j) > (ty * 4 + i)) s[i][j] = -1e30f;
        }

        float corr[4];
#pragma unroll
        for (int i = 0; i < 4; ++i) {
            float mx = s[i][0];
#pragma unroll
            for (int j = 1; j < 8; ++j) mx = fmaxf(mx, s[i][j]);
            mx = fmaxf(mx, __shfl_xor_sync(0xffffffffu, mx, 1));
            mx = fmaxf(mx, __shfl_xor_sync(0xffffffffu, mx, 2));
            mx = fmaxf(mx, __shfl_xor_sync(0xffffffffu, mx, 4));
            float mnew = fmaxf(m_i[i], mx);
            corr[i] = __expf(m_i[i] - mnew);
            m_i[i] = mnew;
            float rs = 0.0f;
#pragma unroll
            for (int j = 0; j < 8; ++j) {
                float p = __expf(s[i][j] - mnew);
                s[i][j] = p;
                rs += p;
            }
            rs += __shfl_xor_sync(0xffffffffu, rs, 1);
            rs += __shfl_xor_sync(0xffffffffu, rs, 2);
            rs += __shfl_xor_sync(0xffffffffu, rs, 4);
            l_i[i] = l_i[i] * corr[i] + rs;
#pragma unroll
            for (int j = 0; j < 8; ++j) o[i][j] *= corr[i];
        }

        __syncthreads();
#pragma unroll
        for (int i = 0; i < 4; ++i) {
            *(float4*)&Ks[rq[i] * 64 + (((tx * 2)     ^ swQ[i]) << 2)] =
                make_float4(s[i][0], s[i][1], s[i][2], s[i][3]);
            *(float4*)&Ks[rq[i] * 64 + (((tx * 2 + 1) ^ swQ[i]) << 2)] =
                make_float4(s[i][4], s[i][5], s[i][6], s[i][7]);
        }
        __syncthreads();

#pragma unroll 4
        for (int kq = 0; kq < 16; ++kq) {
            float p[4][4];
#pragma unroll
            for (int i = 0; i < 4; ++i)
                *(float4*)p[i] = *(const float4*)&Ks[rq[i] * 64 + ((kq ^ swQ[i]) << 2)];
#pragma unroll
            for (int t = 0; t < 4; ++t) {
                int k = kq * 4 + t;
                float4 v0 = *(const float4*)&Vs[k * 64 + tx * 8];
                float4 v1 = *(const float4*)&Vs[k * 64 + tx * 8 + 4];
#pragma unroll
                for (int i = 0; i < 4; ++i) {
                    float pr = p[i][t];
                    o[i][0] = fmaf(pr, v0.x, o[i][0]);
                    o[i][1] = fmaf(pr, v0.y, o[i][1]);
                    o[i][2] = fmaf(pr, v0.z, o[i][2]);
                    o[i][3] = fmaf(pr, v0.w, o[i][3]);
                    o[i][4] = fmaf(pr, v1.x, o[i][4]);
                    o[i][5] = fmaf(pr, v1.y, o[i][5]);
                    o[i][6] = fmaf(pr, v1.z, o[i][6]);
                    o[i][7] = fmaf(pr, v1.w, o[i][7]);
                }
            }
        }
    }

#pragma unroll
    for (int i = 0; i < 4; ++i) {
        float inv = 1.0f / l_i[i];
        int qr = qb * 64 + ty * 4 + i;
        float4 r0 = make_float4(o[i][0] * inv, o[i][1] * inv, o[i][2] * inv, o[i][3] * inv);
        float4 r1 = make_float4(o[i][4] * inv, o[i][5] * inv, o[i][6] * inv, o[i][7] * inv);
        float* dst = out + (size_t)(b * NN + qr) * DD + h * DH + tx * 8;
        *(float4*)(dst)     = r0;
        *(float4*)(dst + 4) = r1;
    }
}

// ---------------------------------------------------------------------------
extern "C" void kernel_launch(void* const* d_in, const int* in_sizes, int n_in,
                              void* d_out, int out_size)
{
    const float* x = (const float*)d_in[0];   // [2,2048,1024] fp32
    const float* w = (const float*)d_in[1];   // [1024,3072] fp32
    float* out = (float*)d_out;               // [2,2048,1024] fp32
    (void)in_sizes; (void)n_in; (void)out_size;

    // bf16 hi/lo splits (+ W transpose), pair-permuted for LDS.64 fragments
    prep_x<<<1024, 256>>>(x);
    prep_w<<<dim3(D3 / 32, DD / 32), dim3(32, 8)>>>(w);

    // bf16x3 QKV GEMM via mma.sync into per-head scratch
    cudaFuncSetAttribute(qkv_gemm_mma,
                         cudaFuncAttributeMaxDynamicSharedMemorySize,
                         GEMM_SMEM_TOTAL);
    qkv_gemm_mma<<<dim3(D3 / 128, MM / 128), 256, GEMM_SMEM_TOTAL>>>();

    // causal attention (fp32)
    cudaFuncSetAttribute(attn_kernel,
                         cudaFuncAttributeMaxDynamicSharedMemorySize,
                         ATT_SMEM_BYTES);
    dim3 g2(NN / 64, HH, BB);      // (32, 16, 2)
    attn_kernel<<<g2, 128, ATT_SMEM_BYTES>>>(out);
}

// round 10
// speedup vs baseline: 2.4935x; 1.8720x over previous
#include <cuda_runtime.h>
#include <cuda_bf16.h>
#include <cstdint>

// Problem constants
#define BB 2
#define NN 2048
#define HH 16
#define DH 64
#define DD 1024          // HH*DH
#define D3 3072          // 3*DD
#define MM 4096          // BB*NN

// Scratch: QKV laid out [part(q/k/v)][B][H][N][Dh], fp32
__device__ float g_qkv[3u * BB * HH * NN * DH];
// GEMM operands: bf16 hi/lo, b32-pair order per k16 block: [p0,p4,p1,p5,p2,p6,p3,p7]
__device__ __nv_bfloat16 g_xhi[(size_t)MM * DD];
__device__ __nv_bfloat16 g_xlo[(size_t)MM * DD];
__device__ __nv_bfloat16 g_whiT[(size_t)D3 * DD];
__device__ __nv_bfloat16 g_wloT[(size_t)D3 * DD];
// Attention operands (bf16 hi/lo, pair-permuted)
__device__ __nv_bfloat16 g_qh[(size_t)BB * HH * NN * DH];   // [bh][n][d], prescaled 1/8
__device__ __nv_bfloat16 g_ql[(size_t)BB * HH * NN * DH];
__device__ __nv_bfloat16 g_kh[(size_t)BB * HH * NN * DH];   // [bh][n][d]
__device__ __nv_bfloat16 g_kl[(size_t)BB * HH * NN * DH];
__device__ __nv_bfloat16 g_vh[(size_t)BB * HH * DH * NN];   // [bh][d][n] (transposed)
__device__ __nv_bfloat16 g_vl[(size_t)BB * HH * DH * NN];

// ---------------------------------------------------------------------------
// helpers
// ---------------------------------------------------------------------------
#define CP_ASYNC16(dst_u32, gptr)                                              \
    asm volatile("cp.async.cg.shared.global [%0], [%1], 16;"                    \
                 :: "r"(dst_u32), "l"(__cvta_generic_to_global(gptr)))
#define CP_COMMIT() asm volatile("cp.async.commit_group;" ::: "memory")
#define CP_WAIT1()  asm volatile("cp.async.wait_group 1;" ::: "memory")
#define CP_WAIT0()  asm volatile("cp.async.wait_group 0;" ::: "memory")

__device__ __forceinline__ uint32_t smem_u32(const void* p) {
    uint32_t a;
    asm("{ .reg .u64 t; cvta.to.shared.u64 t, %1; cvt.u32.u64 %0, t; }"
        : "=r"(a) : "l"(p));
    return a;
}

// mma.sync m16n8k16 bf16: d += a * b  (f32 accumulate)
__device__ __forceinline__ void mma_bf16(float* d,
                                         uint32_t a0, uint32_t a1, uint32_t a2, uint32_t a3,
                                         uint32_t b0, uint32_t b1) {
    asm volatile(
        "mma.sync.aligned.m16n8k16.row.col.f32.bf16.bf16.f32 "
        "{%0,%1,%2,%3}, {%4,%5,%6,%7}, {%8,%9}, {%0,%1,%2,%3};"
        : "+f"(d[0]), "+f"(d[1]), "+f"(d[2]), "+f"(d[3])
        : "r"(a0), "r"(a1), "r"(a2), "r"(a3), "r"(b0), "r"(b1));
}

__device__ __forceinline__ uint32_t pack_bf16(float x0, float x1) {
    __nv_bfloat16 h0 = __float2bfloat16_rn(x0);
    __nv_bfloat16 h1 = __float2bfloat16_rn(x1);
    return (uint32_t)__bfloat16_as_ushort(h0) |
           ((uint32_t)__bfloat16_as_ushort(h1) << 16);
}

// split a float pair into packed bf16 hi and lo words
__device__ __forceinline__ void split2(float x0, float x1, uint32_t& h, uint32_t& l) {
    __nv_bfloat16 h0 = __float2bfloat16_rn(x0);
    __nv_bfloat16 h1 = __float2bfloat16_rn(x1);
    h = (uint32_t)__bfloat16_as_ushort(h0) |
        ((uint32_t)__bfloat16_as_ushort(h1) << 16);
    l = pack_bf16(x0 - __bfloat162float(h0), x1 - __bfloat162float(h1));
}

__device__ __forceinline__ int dpos8(int p) {   // dest slot of source pair p in 8-block
    return ((p & 3) << 1) | (p >> 2);
}

// ---------------------------------------------------------------------------
// GEMM prep: bf16 hi/lo split, pair-permutation (+ transpose for W)
// ---------------------------------------------------------------------------
__global__ __launch_bounds__(256)
void prep_x(const float* __restrict__ X)
{
    const size_t n16 = (size_t)MM * DD / 16;
    for (size_t i = (size_t)blockIdx.x * 256 + threadIdx.x; i < n16;
         i += (size_t)gridDim.x * 256) {
        const float* src = X + i * 16;
        float s[16];
        *(float4*)(s)      = ((const float4*)src)[0];
        *(float4*)(s + 4)  = ((const float4*)src)[1];
        *(float4*)(s + 8)  = ((const float4*)src)[2];
        *(float4*)(s + 12) = ((const float4*)src)[3];
        float hi[16], lo[16];
#pragma unroll
        for (int k = 0; k < 16; ++k) {
            __nv_bfloat16 h = __float2bfloat16_rn(s[k]);
            hi[k] = __bfloat162float(h);
            lo[k] = s[k] - hi[k];
        }
        const int pp[8] = {0, 4, 1, 5, 2, 6, 3, 7};
        uint32_t ph[8], pl[8];
#pragma unroll
        for (int d = 0; d < 8; ++d) {
            int p = pp[d];
            ph[d] = pack_bf16(hi[2 * p], hi[2 * p + 1]);
            pl[d] = pack_bf16(lo[2 * p], lo[2 * p + 1]);
        }
        uint32_t* dh = (uint32_t*)g_xhi + i * 8;
        uint32_t* dl = (uint32_t*)g_xlo + i * 8;
        *(uint4*)(dh)     = make_uint4(ph[0], ph[1], ph[2], ph[3]);
        *(uint4*)(dh + 4) = make_uint4(ph[4], ph[5], ph[6], ph[7]);
        *(uint4*)(dl)     = make_uint4(pl[0], pl[1], pl[2], pl[3]);
        *(uint4*)(dl + 4) = make_uint4(pl[4], pl[5], pl[6], pl[7]);
    }
}

__device__ __forceinline__ int kperm16(int k) {
    int p = (k >> 1) & 7;
    int d = ((p & 3) << 1) | (p >> 2);
    return (k & ~15) | (d * 2) | (k & 1);
}

__global__ __launch_bounds__(256)
void prep_w(const float* __restrict__ W)
{
    __shared__ float t[32][33];
    const int n0 = blockIdx.x * 32;
    const int k0 = blockIdx.y * 32;
    const int tx = threadIdx.x, ty = threadIdx.y;   // (32, 8)
#pragma unroll
    for (int rr = 0; rr < 32; rr += 8)
        t[ty + rr][tx] = W[(size_t)(k0 + ty + rr) * D3 + n0 + tx];
    __syncthreads();
#pragma unroll
    for (int rr = 0; rr < 32; rr += 8) {
        float v  = t[tx][ty + rr];
        __nv_bfloat16 h = __float2bfloat16_rn(v);
        float hf = __bfloat162float(h);
        __nv_bfloat16 l = __float2bfloat16_rn(v - hf);
        size_t base = (size_t)(n0 + ty + rr) * DD + k0 + kperm16(tx);
        g_whiT[base] = h;
        g_wloT[base] = l;
    }
}

// ---------------------------------------------------------------------------
// bf16x3 QKV GEMM via mma.sync m16n8k16 (unchanged from R9, passing).
// ---------------------------------------------------------------------------
#define ROWW 20
#define OAHI 0
#define OALO 2560
#define OBHI 5120
#define OBLO 7680
#define ST_B32 10240
#define GEMM_SMEM_TOTAL (2 * ST_B32 * 4)

__device__ __forceinline__ void gemm_load(int kt, uint32_t st_u32,
                                          int m0, int n0, int tid)
{
    const int k0 = kt * 32;
#pragma unroll
    for (int it = 0; it < 2; ++it) {
        int j   = it * 256 + tid;
        int row = j >> 2;
        int q   = (j & 3);
        uint32_t doff = (uint32_t)(row * ROWW + q * 4) * 4;
        CP_ASYNC16(st_u32 + OAHI * 4 + doff, g_xhi  + (size_t)(m0 + row) * DD + k0 + q * 8);
        CP_ASYNC16(st_u32 + OALO * 4 + doff, g_xlo  + (size_t)(m0 + row) * DD + k0 + q * 8);
        CP_ASYNC16(st_u32 + OBHI * 4 + doff, g_whiT + (size_t)(n0 + row) * DD + k0 + q * 8);
        CP_ASYNC16(st_u32 + OBLO * 4 + doff, g_wloT + (size_t)(n0 + row) * DD + k0 + q * 8);
    }
}

__global__ __launch_bounds__(256, 2)
void qkv_gemm_mma()
{
    extern __shared__ float sm[];
    const int tid   = threadIdx.x;
    const int wid   = tid >> 5;
    const int lane  = tid & 31;
    const int warpm = wid & 3;
    const int warpn = wid >> 2;
    const int c     = lane & 3;
    const int g     = lane >> 2;
    const int n0    = blockIdx.x * 128;
    const int m0    = blockIdx.y * 128;

    const uint32_t* st[2] = {(const uint32_t*)sm, (const uint32_t*)sm + ST_B32};
    uint32_t stu[2] = {smem_u32(sm), smem_u32(sm + ST_B32)};

    float acc[2][8][4];
#pragma unroll
    for (int mt = 0; mt < 2; ++mt)
#pragma unroll
        for (int nt = 0; nt < 8; ++nt)
#pragma unroll
            for (int v = 0; v < 4; ++v) acc[mt][nt][v] = 0.0f;

    gemm_load(0, stu[0], m0, n0, tid); CP_COMMIT();
    gemm_load(1, stu[1], m0, n0, tid); CP_COMMIT();

    for (int kt = 0; kt < 32; ++kt) {
        const int buf = kt & 1;
        if (kt < 30) { CP_WAIT1(); } else { CP_WAIT0(); }
        __syncthreads();

        const uint32_t* S = st[buf];
#pragma unroll
        for (int ks = 0; ks < 2; ++ks) {
            const int kc = ks * 8 + 2 * c;
            uint2 ah[2][2], al[2][2];
#pragma unroll
            for (int mt = 0; mt < 2; ++mt) {
                int rbase = warpm * 32 + mt * 16 + g;
                ah[mt][0] = *(const uint2*)&S[OAHI + rbase * ROWW + kc];
                ah[mt][1] = *(const uint2*)&S[OAHI + (rbase + 8) * ROWW + kc];
                al[mt][0] = *(const uint2*)&S[OALO + rbase * ROWW + kc];
                al[mt][1] = *(const uint2*)&S[OALO + (rbase + 8) * ROWW + kc];
            }
#pragma unroll
            for (int nt = 0; nt < 8; ++nt) {
                int nb = (warpn * 64 + nt * 8 + g) * ROWW + kc;
                uint2 bh = *(const uint2*)&S[OBHI + nb];
                uint2 bl = *(const uint2*)&S[OBLO + nb];
#pragma unroll
                for (int mt = 0; mt < 2; ++mt) {
                    mma_bf16(acc[mt][nt], ah[mt][0].x, ah[mt][1].x,
                             ah[mt][0].y, ah[mt][1].y, bh.x, bh.y);
                    mma_bf16(acc[mt][nt], ah[mt][0].x, ah[mt][1].x,
                             ah[mt][0].y, ah[mt][1].y, bl.x, bl.y);
                    mma_bf16(acc[mt][nt], al[mt][0].x, al[mt][1].x,
                             al[mt][0].y, al[mt][1].y, bh.x, bh.y);
                }
            }
        }
        __syncthreads();
        if (kt + 2 < 32) {
            gemm_load(kt + 2, stu[buf], m0, n0, tid);
            CP_COMMIT();
        }
    }

#pragma unroll
    for (int mt = 0; mt < 2; ++mt) {
#pragma unroll
        for (int nt = 0; nt < 8; ++nt) {
            int colg = n0 + warpn * 64 + nt * 8 + 2 * c;
            int part = colg >> 10;
            int pc   = colg & 1023;
            int h    = pc >> 6;
            int dh   = pc & 63;
#pragma unroll
            for (int rh = 0; rh < 2; ++rh) {
                int mg  = m0 + warpm * 32 + mt * 16 + g + rh * 8;
                int b   = mg >> 11;
                int seq = mg & 2047;
                float* dst = g_qkv + ((size_t)((part * BB + b) * HH + h) * NN + seq) * DH + dh;
                *(float2*)dst = make_float2(acc[mt][nt][rh * 2], acc[mt][nt][rh * 2 + 1]);
            }
        }
    }
}

// ---------------------------------------------------------------------------
// Attention prep: Q/K rows -> bf16 hi/lo pair-permuted (Q prescaled 1/8);
// V -> transposed [d][n] bf16 hi/lo pair-permuted along n.
// ---------------------------------------------------------------------------
__global__ __launch_bounds__(256)
void prep_attn_qk()
{
    int cidx = blockIdx.x * 256 + threadIdx.x;       // 0..524287
    int row  = cidx >> 2;                            // 0..131071 (Q rows then K rows)
    int ch   = cidx & 3;                             // 16-elem chunk within row
    int part = row >> 16;                            // 0 = Q, 1 = K
    const float* src = g_qkv + (size_t)row * 64 + ch * 16;
    float sc = part ? 1.0f : 0.125f;
    float s[16];
    *(float4*)(s)      = ((const float4*)src)[0];
    *(float4*)(s + 4)  = ((const float4*)src)[1];
    *(float4*)(s + 8)  = ((const float4*)src)[2];
    *(float4*)(s + 12) = ((const float4*)src)[3];
#pragma unroll
    for (int k = 0; k < 16; ++k) s[k] *= sc;
    const int pp[8] = {0, 4, 1, 5, 2, 6, 3, 7};
    uint32_t ph[8], pl[8];
#pragma unroll
    for (int d = 0; d < 8; ++d) {
        int p = pp[d];
        split2(s[2 * p], s[2 * p + 1], ph[d], pl[d]);
    }
    size_t off = ((size_t)(row & 65535) * 32) + ch * 8;   // b32 units
    uint32_t* dh = (part ? (uint32_t*)g_kh : (uint32_t*)g_qh) + off;
    uint32_t* dl = (part ? (uint32_t*)g_kl : (uint32_t*)g_ql) + off;
    *(uint4*)(dh)     = make_uint4(ph[0], ph[1], ph[2], ph[3]);
    *(uint4*)(dh + 4) = make_uint4(ph[4], ph[5], ph[6], ph[7]);
    *(uint4*)(dl)     = make_uint4(pl[0], pl[1], pl[2], pl[3]);
    *(uint4*)(dl + 4) = make_uint4(pl[4], pl[5], pl[6], pl[7]);
}

__global__ __launch_bounds__(256)
void prep_attn_v()
{
    __shared__ float t[64][65];
    const int n0 = blockIdx.x * 64;
    const int h  = blockIdx.y;
    const int b  = blockIdx.z;
    const int bh = b * HH + h;
    const int tid = threadIdx.x;
    const float* Vg = g_qkv + (size_t)((2 * BB + b) * HH + h) * NN * DH;
#pragma unroll
    for (int i = 0; i < 16; ++i) {
        int lin = i * 256 + tid;
        int r = lin >> 6, d = lin & 63;
        t[r][d] = Vg[(size_t)(n0 + r) * 64 + d];
    }
    __syncthreads();
    const int d  = tid >> 2;
    const int qq = tid & 3;
    uint32_t* vh = (uint32_t*)g_vh + ((size_t)bh * 64 + d) * 1024;
    uint32_t* vl = (uint32_t*)g_vl + ((size_t)bh * 64 + d) * 1024;
#pragma unroll
    for (int i = 0; i < 8; ++i) {
        int npl = qq * 8 + i;
        float p0 = t[2 * npl][d];
        float p1 = t[2 * npl + 1][d];
        uint32_t hw, lw;
        split2(p0, p1, hw, lw);
        int npg = (n0 >> 1) + npl;
        int dst = (npg & ~7) + dpos8(npg & 7);
        vh[dst] = hw;
        vl[dst] = lw;
    }
}

// ---------------------------------------------------------------------------
// bf16x3 causal flash attention via mma.sync m16n8k16.
// CTA = 256 thr (8 warps), q-tile 128 (16 rows per warp -> warp-local softmax).
// K/V cp.async double-buffered; P stays in registers (S D-frag == PV A-frag).
// ---------------------------------------------------------------------------
#define ROWK 36                 // b32 per K smem row (32 data + 4 pad)
#define ROWV 68                 // b32 per V smem row (64 data + 4 pad)
#define KSTG (128 * ROWK)       // 4608 b32
#define VSTG (64 * ROWV)        // 4352 b32
#define ATT_SMEM_B32 (4 * KSTG + 4 * VSTG)
#define ATT_SMEM_BYTES (ATT_SMEM_B32 * 4)

__device__ __forceinline__ void attn_load_kv(
    int kt, int s, int tid, uint32_t sbase,
    const __nv_bfloat16* khg, const __nv_bfloat16* klg,
    const __nv_bfloat16* vhg, const __nv_bfloat16* vlg)
{
    const uint32_t okh = (s ? KSTG : 0) * 4;
    const uint32_t okl = (2 * KSTG + (s ? KSTG : 0)) * 4;
    const uint32_t ovh = (4 * KSTG + (s ? VSTG : 0)) * 4;
    const uint32_t ovl = (4 * KSTG + 2 * VSTG + (s ? VSTG : 0)) * 4;
#pragma unroll
    for (int it = 0; it < 4; ++it) {
        int idx = it * 256 + tid;
        int row = idx >> 3, ch = idx & 7;
        uint32_t doff = (uint32_t)(row * ROWK + ch * 4) * 4;
        size_t so = (size_t)(kt * 128 + row) * 64 + ch * 8;
        CP_ASYNC16(sbase + okh + doff, khg + so);
        CP_ASYNC16(sbase + okl + doff, klg + so);
    }
#pragma unroll
    for (int it = 0; it < 4; ++it) {
        int idx = it * 256 + tid;
        int row = idx >> 4, ch = idx & 15;
        uint32_t doff = (uint32_t)(row * ROWV + ch * 4) * 4;
        size_t so = (size_t)row * NN + kt * 128 + ch * 8;
        CP_ASYNC16(sbase + ovh + doff, vhg + so);
        CP_ASYNC16(sbase + ovl + doff, vlg + so);
    }
}

__global__ __launch_bounds__(256, 1)
void attn_mma(float* __restrict__ out)
{
    extern __shared__ float smf[];
    uint32_t* su = (uint32_t*)smf;
    const uint32_t sbase = smem_u32(smf);
    const int tid  = threadIdx.x;
    const int w    = tid >> 5;
    const int lane = tid & 31;
    const int g    = lane >> 2;
    const int c    = lane & 3;
    const int qb   = (int)gridDim.x - 1 - blockIdx.x;   // heavy tiles first
    const int h    = blockIdx.y;
    const int b    = blockIdx.z;
    const int bh   = b * HH + h;

    const __nv_bfloat16* khg = g_kh + (size_t)bh * NN * DH;
    const __nv_bfloat16* klg = g_kl + (size_t)bh * NN * DH;
    const __nv_bfloat16* vhg = g_vh + (size_t)bh * DH * NN;
    const __nv_bfloat16* vlg = g_vl + (size_t)bh * DH * NN;

    // Q fragments, register-resident for the whole CTA lifetime
    uint2 qfh[4][2], qfl[4][2];
    {
        const uint32_t* qh32 = (const uint32_t*)g_qh;
        const uint32_t* ql32 = (const uint32_t*)g_ql;
        size_t r0 = (size_t)bh * NN + qb * 128 + w * 16 + g;
#pragma unroll
        for (int kd = 0; kd < 4; ++kd) {
            qfh[kd][0] = *(const uint2*)&qh32[r0 * 32 + kd * 8 + 2 * c];
            qfh[kd][1] = *(const uint2*)&qh32[(r0 + 8) * 32 + kd * 8 + 2 * c];
            qfl[kd][0] = *(const uint2*)&ql32[r0 * 32 + kd * 8 + 2 * c];
            qfl[kd][1] = *(const uint2*)&ql32[(r0 + 8) * 32 + kd * 8 + 2 * c];
        }
    }

    float oa[8][4];
#pragma unroll
    for (int nt = 0; nt < 8; ++nt)
#pragma unroll
        for (int v = 0; v < 4; ++v) oa[nt][v] = 0.0f;
    float m0 = -1e30f, m1 = -1e30f, l0 = 0.0f, l1 = 0.0f;

    attn_load_kv(0, 0, tid, sbase, khg, klg, vhg, vlg);
    CP_COMMIT();
    if (qb >= 1) attn_load_kv(1, 1, tid, sbase, khg, klg, vhg, vlg);
    CP_COMMIT();

    for (int kt = 0; kt <= qb; ++kt) {
        if (kt < qb) { CP_WAIT1(); } else { CP_WAIT0(); }
        __syncthreads();
        const int s = kt & 1;
        const uint32_t* KH = su + (s ? KSTG : 0);
        const uint32_t* KL = su + 2 * KSTG + (s ? KSTG : 0);
        const uint32_t* VH = su + 4 * KSTG + (s ? VSTG : 0);
        const uint32_t* VL = su + 4 * KSTG + 2 * VSTG + (s ? VSTG : 0);

        // S = Q @ K^T (bf16x3), 16 n8-tiles per warp
        float sa[16][4];
#pragma unroll
        for (int nt = 0; nt < 16; ++nt) {
            sa[nt][0] = 0.0f; sa[nt][1] = 0.0f; sa[nt][2] = 0.0f; sa[nt][3] = 0.0f;
        }
#pragma unroll
        for (int kd = 0; kd < 4; ++kd) {
#pragma unroll
            for (int nt = 0; nt < 16; ++nt) {
                int a = (8 * nt + g) * ROWK + 8 * kd + 2 * c;
                uint2 kh2 = *(const uint2*)&KH[a];
                uint2 kl2 = *(const uint2*)&KL[a];
                mma_bf16(sa[nt], qfh[kd][0].x, qfh[kd][1].x,
                         qfh[kd][0].y, qfh[kd][1].y, kh2.x, kh2.y);
                mma_bf16(sa[nt], qfh[kd][0].x, qfh[kd][1].x,
                         qfh[kd][0].y, qfh[kd][1].y, kl2.x, kl2.y);
                mma_bf16(sa[nt], qfl[kd][0].x, qfl[kd][1].x,
                         qfl[kd][0].y, qfl[kd][1].y, kh2.x, kh2.y);
            }
        }

        // causal mask on the diagonal tile
        if (kt == qb) {
            int r0 = 16 * w + g, r1 = r0 + 8;
#pragma unroll
            for (int nt = 0; nt < 16; ++nt) {
                int c0 = 8 * nt + 2 * c, c1 = c0 + 1;
                if (c0 > r0) sa[nt][0] = -1e30f;
                if (c1 > r0) sa[nt][1] = -1e30f;
                if (c0 > r1) sa[nt][2] = -1e30f;
                if (c1 > r1) sa[nt][3] = -1e30f;
            }
        }

        // warp-local online softmax (rows g and g+8 of this warp's 16)
        float mx0 = -1e30f, mx1 = -1e30f;
#pragma unroll
        for (int nt = 0; nt < 16; ++nt) {
            mx0 = fmaxf(mx0, fmaxf(sa[nt][0], sa[nt][1]));
            mx1 = fmaxf(mx1, fmaxf(sa[nt][2], sa[nt][3]));
        }
        mx0 = fmaxf(mx0, __shfl_xor_sync(0xffffffffu, mx0, 1));
        mx0 = fmaxf(mx0, __shfl_xor_sync(0xffffffffu, mx0, 2));
        mx1 = fmaxf(mx1, __shfl_xor_sync(0xffffffffu, mx1, 1));
        mx1 = fmaxf(mx1, __shfl_xor_sync(0xffffffffu, mx1, 2));
        float mn0 = fmaxf(m0, mx0), mn1 = fmaxf(m1, mx1);
        float cr0 = __expf(m0 - mn0), cr1 = __expf(m1 - mn1);
        m0 = mn0; m1 = mn1;
        float rs0 = 0.0f, rs1 = 0.0f;
#pragma unroll
        for (int nt = 0; nt < 16; ++nt) {
            sa[nt][0] = __expf(sa[nt][0] - mn0); rs0 += sa[nt][0];
            sa[nt][1] = __expf(sa[nt][1] - mn0); rs0 += sa[nt][1];
            sa[nt][2] = __expf(sa[nt][2] - mn1); rs1 += sa[nt][2];
            sa[nt][3] = __expf(sa[nt][3] - mn1); rs1 += sa[nt][3];
        }
        rs0 += __shfl_xor_sync(0xffffffffu, rs0, 1);
        rs0 += __shfl_xor_sync(0xffffffffu, rs0, 2);
        rs1 += __shfl_xor_sync(0xffffffffu, rs1, 1);
        rs1 += __shfl_xor_sync(0xffffffffu, rs1, 2);
        l0 = l0 * cr0 + rs0;
        l1 = l1 * cr1 + rs1;
#pragma unroll
        for (int nt = 0; nt < 8; ++nt) {
            oa[nt][0] *= cr0; oa[nt][1] *= cr0;
            oa[nt][2] *= cr1; oa[nt][3] *= cr1;
        }

        // O += P @ V (bf16x3); P fragments packed straight from sa registers
#pragma unroll
        for (int kb = 0; kb < 8; ++kb) {
            uint32_t ah0, ah1, ah2, ah3, al0, al1, al2, al3;
            split2(sa[2 * kb][0],     sa[2 * kb][1],     ah0, al0);
            split2(sa[2 * kb][2],     sa[2 * kb][3],     ah1, al1);
            split2(sa[2 * kb + 1][0], sa[2 * kb + 1][1], ah2, al2);
            split2(sa[2 * kb + 1][2], sa[2 * kb + 1][3], ah3, al3);
#pragma unroll
            for (int nt = 0; nt < 8; ++nt) {
                int a = (8 * nt + g) * ROWV + 8 * kb + 2 * c;
                uint2 vh2 = *(const uint2*)&VH[a];
                uint2 vl2 = *(const uint2*)&VL[a];
                mma_bf16(oa[nt], ah0, ah1, ah2, ah3, vh2.x, vh2.y);
                mma_bf16(oa[nt], al0, al1, al2, al3, vh2.x, vh2.y);
                mma_bf16(oa[nt], ah0, ah1, ah2, ah3, vl2.x, vl2.y);
            }
        }

        __syncthreads();
        if (kt + 2 <= qb) {
            attn_load_kv(kt + 2, s, tid, sbase, khg, klg, vhg, vlg);
            CP_COMMIT();
        }
    }

    // epilogue: out[b][n][h*64 + d]
    float i0 = 1.0f / l0, i1 = 1.0f / l1;
    int r0 = qb * 128 + 16 * w + g;
    float* o0 = out + ((size_t)b * NN + r0) * DD + h * 64;
    float* o1 = o0 + (size_t)8 * DD;
#pragma unroll
    for (int nt = 0; nt < 8; ++nt) {
        *(float2*)&o0[8 * nt + 2 * c] = make_float2(oa[nt][0] * i0, oa[nt][1] * i0);
        *(float2*)&o1[8 * nt + 2 * c] = make_float2(oa[nt][2] * i1, oa[nt][3] * i1);
    }
}

// ---------------------------------------------------------------------------
extern "C" void kernel_launch(void* const* d_in, const int* in_sizes, int n_in,
                              void* d_out, int out_size)
{
    const float* x = (const float*)d_in[0];   // [2,2048,1024] fp32
    const float* w = (const float*)d_in[1];   // [1024,3072] fp32
    float* out = (float*)d_out;               // [2,2048,1024] fp32
    (void)in_sizes; (void)n_in; (void)out_size;

    // GEMM operand prep
    prep_x<<<1024, 256>>>(x);
    prep_w<<<dim3(D3 / 32, DD / 32), dim3(32, 8)>>>(w);

    // bf16x3 QKV GEMM
    cudaFuncSetAttribute(qkv_gemm_mma,
                         cudaFuncAttributeMaxDynamicSharedMemorySize,
                         GEMM_SMEM_TOTAL);
    qkv_gemm_mma<<<dim3(D3 / 128, MM / 128), 256, GEMM_SMEM_TOTAL>>>();

    // attention operand prep (Q/K rows, V transpose)
    prep_attn_qk<<<2048, 256>>>();
    prep_attn_v<<<dim3(NN / 64, HH, BB), 256>>>();

    // bf16x3 mma flash attention
    cudaFuncSetAttribute(attn_mma,
                         cudaFuncAttributeMaxDynamicSharedMemorySize,
                         ATT_SMEM_BYTES);
    attn_mma<<<dim3(NN / 128, HH, BB), 256, ATT_SMEM_BYTES>>>(out);
}